// round 2
// baseline (speedup 1.0000x reference)
#include <cuda_runtime.h>

// ---------------------------------------------------------------------------
// LSTMModel: 4-layer LSTM (H=50) over B=1024, T=512, IN=7, + FC(25) + FC(1).
// R2: packed fma.rn.f32x2 along k (weights pre-packed as (w_k, w_{k+1}) u64),
// activations transposed to [b][k] so LDS.128 yields two f32x2 operands.
// c kept in registers. 128 CTAs x 8 batch rows, no cross-CTA sync.
// ---------------------------------------------------------------------------

#define TT  512
#define BB  1024
#define HH  50
#define GG  200           // 4*H gates
#define NB  8             // batch rows per CTA
#define NCTA (BB / NB)    // 128
#define IN0 7
#define FC1 25

__device__ float g_bufA[TT * BB * HH];
__device__ float g_bufB[TT * BB * HH];
__device__ float g_xT[TT * BB * IN0];

__device__ __forceinline__ float sigmf(float x) {
    return __fdividef(1.0f, 1.0f + __expf(-x));
}
__device__ __forceinline__ float tanhfast(float x) {
    float e = __expf(2.0f * x);
    return 1.0f - __fdividef(2.0f, e + 1.0f);
}

#define FMA2(acc, w, h) \
    asm("fma.rn.f32x2 %0, %1, %2, %0;" : "+l"(acc) : "l"(w), "l"(h))
#define PACK2(out, lo, hi) \
    asm("mov.b64 %0, {%1, %2};" : "=l"(out) : "f"(lo), "f"(hi))
#define UNPACK2(lo, hi, in) \
    asm("mov.b64 {%0, %1}, %2;" : "=f"(lo), "=f"(hi) : "l"(in))

// ---------------------------------------------------------------------------
__global__ void transpose_x_kernel(const float* __restrict__ x) {
    int idx = blockIdx.x * blockDim.x + threadIdx.x;
    if (idx < BB * TT * IN0) {
        int k = idx % IN0;
        int t = (idx / IN0) % TT;
        int b = idx / (IN0 * TT);
        g_xT[(t * BB + b) * IN0 + k] = x[idx];
    }
}

// ---------------------------------------------------------------------------
// One LSTM layer over the whole sequence for an 8-row batch tile.
// ---------------------------------------------------------------------------
template <int KIN>
__global__ void __launch_bounds__(256, 1) lstm_layer_kernel(
    int src, int dst,
    const float* __restrict__ Wih,   // [GG][KIN]
    const float* __restrict__ Whh,   // [GG][HH]
    const float* __restrict__ bih,
    const float* __restrict__ bhh)
{
    constexpr int K     = KIN + HH;
    constexpr int KQ    = (K + 3) / 4;      // k-quads
    constexpr int K_PAD = KQ * 4;

    const float* __restrict__ in_seq =
        (src == 0) ? g_xT : ((src == 1) ? g_bufA : g_bufB);
    float* __restrict__ out_seq = (dst == 1) ? g_bufA : g_bufB;

    __shared__ float sh_in[2][NB][K_PAD];   // [x | h | zero-pad]
    __shared__ float sh_g[GG][NB];

    const int tid = threadIdx.x;
    const int b0  = blockIdx.x * NB;
    constexpr int PF = (KIN * NB + 255) / 256;

    // ---- per-thread packed weight row: (w_{4q}, w_{4q+1}), (w_{4q+2}, w_{4q+3})
    unsigned long long wq[2 * KQ];
    float bg = 0.0f;
    if (tid < GG) {
#pragma unroll
        for (int q = 0; q < KQ; q++) {
#pragma unroll
            for (int p = 0; p < 2; p++) {
                int k0 = 4 * q + 2 * p;
                float w0 = (k0     < KIN) ? Wih[tid * KIN + k0]
                         : (k0     < K  ) ? Whh[tid * HH + (k0 - KIN)] : 0.0f;
                float w1 = (k0 + 1 < KIN) ? Wih[tid * KIN + k0 + 1]
                         : (k0 + 1 < K  ) ? Whh[tid * HH + (k0 + 1 - KIN)] : 0.0f;
                PACK2(wq[2 * q + p], w0, w1);
            }
        }
        bg = bih[tid] + bhh[tid];
    }

    // ---- c state in registers (update mapping fixed: jj = tid>>2, b = (tid&3)*2 + q)
    float c0 = 0.0f, c1 = 0.0f;
    const int jj = tid >> 2;
    const int bb = (tid & 3) * 2;

    // ---- zero both buffers (h0 = 0, pad = 0), then stage x(t=0) into buf 0
    for (int i = tid; i < 2 * NB * K_PAD; i += 256)
        (&sh_in[0][0][0])[i] = 0.0f;
    __syncthreads();
    for (int i = tid; i < KIN * NB; i += 256) {
        int b = i % NB, k = i / NB;
        sh_in[0][b][k] = in_seq[(0 * BB + b0 + b) * KIN + k];
    }
    __syncthreads();

    int buf = 0;
    for (int t = 0; t < TT; t++) {
        // ---- prefetch next-step input into registers
        float pf[PF];
        const bool has_next = (t + 1 < TT);
        if (has_next) {
#pragma unroll
            for (int j = 0; j < PF; j++) {
                int i = tid + j * 256;
                if (i < KIN * NB) {
                    int b = i % NB, k = i / NB;
                    pf[j] = in_seq[((t + 1) * BB + b0 + b) * KIN + k];
                }
            }
        }

        // ---- gate phase: acc2[b] accumulates (even-k sum, odd-k sum) packed
        if (tid < GG) {
            unsigned long long acc2[NB];
#pragma unroll
            for (int b = 0; b < NB; b++) acc2[b] = 0ull;

#pragma unroll 2
            for (int q = 0; q < KQ; q++) {
                unsigned long long w0 = wq[2 * q];
                unsigned long long w1 = wq[2 * q + 1];
#pragma unroll
                for (int b = 0; b < NB; b++) {
                    ulonglong2 hv =
                        *(const ulonglong2*)&sh_in[buf][b][4 * q];
                    FMA2(acc2[b], w0, hv.x);
                    FMA2(acc2[b], w1, hv.y);
                }
            }

            float gv[NB];
#pragma unroll
            for (int b = 0; b < NB; b++) {
                float lo, hi;
                UNPACK2(lo, hi, acc2[b]);
                gv[b] = lo + hi + bg;
            }
            *(float4*)&sh_g[tid][0] = make_float4(gv[0], gv[1], gv[2], gv[3]);
            *(float4*)&sh_g[tid][4] = make_float4(gv[4], gv[5], gv[6], gv[7]);
        }

        // ---- park prefetched x into next buffer's x-slice
        if (has_next) {
#pragma unroll
            for (int j = 0; j < PF; j++) {
                int i = tid + j * 256;
                if (i < KIN * NB) {
                    int b = i % NB, k = i / NB;
                    sh_in[buf ^ 1][b][k] = pf[j];
                }
            }
        }
        __syncthreads();

        // ---- update phase: thread = (unit jj, batch pair bb..bb+1)
        if (tid < GG) {
#pragma unroll
            for (int q = 0; q < 2; q++) {
                int b = bb + q;
                float ig = sigmf(sh_g[jj][b]);
                float fg = sigmf(sh_g[HH + jj][b]);
                float gg = tanhfast(sh_g[2 * HH + jj][b]);
                float og = sigmf(sh_g[3 * HH + jj][b]);
                float& c = q ? c1 : c0;
                c = fg * c + ig * gg;
                float h = og * tanhfast(c);
                sh_in[buf ^ 1][b][KIN + jj] = h;   // h into next buffer
                out_seq[(t * BB + b0 + b) * HH + jj] = h;
            }
        }
        buf ^= 1;
        __syncthreads();
    }
}

// ---------------------------------------------------------------------------
__global__ void fc_head_kernel(int src,
                               const float* __restrict__ W1,
                               const float* __restrict__ b1,
                               const float* __restrict__ W2,
                               const float* __restrict__ b2,
                               float* __restrict__ out)
{
    const float* __restrict__ hseq = (src == 1) ? g_bufA : g_bufB;
    __shared__ float sW1[FC1 * HH];
    __shared__ float sW2[FC1];
    __shared__ float sb1[FC1];

    int tid = threadIdx.x;
    for (int i = tid; i < FC1 * HH; i += 256) sW1[i] = W1[i];
    if (tid < FC1) { sW2[tid] = W2[tid]; sb1[tid] = b1[tid]; }
    __syncthreads();

    int b = blockIdx.x * blockDim.x + tid;
    if (b < BB) {
        const float* h = &hseq[((TT - 1) * BB + b) * HH];
        float hreg[HH];
#pragma unroll
        for (int k = 0; k < HH; k++) hreg[k] = h[k];
        float o = b2[0];
#pragma unroll
        for (int j = 0; j < FC1; j++) {
            float a = sb1[j];
#pragma unroll
            for (int k = 0; k < HH; k++) a += sW1[j * HH + k] * hreg[k];
            o += sW2[j] * fmaxf(a, 0.0f);
        }
        out[b] = o;
    }
}

// ---------------------------------------------------------------------------
extern "C" void kernel_launch(void* const* d_in, const int* in_sizes, int n_in,
                              void* d_out, int out_size)
{
    const float* x    = (const float*)d_in[0];
    const float* Wih0 = (const float*)d_in[1];
    const float* Whh0 = (const float*)d_in[2];
    const float* bih0 = (const float*)d_in[3];
    const float* bhh0 = (const float*)d_in[4];
    const float* Wih1 = (const float*)d_in[5];
    const float* Whh1 = (const float*)d_in[6];
    const float* bih1 = (const float*)d_in[7];
    const float* bhh1 = (const float*)d_in[8];
    const float* Wih2 = (const float*)d_in[9];
    const float* Whh2 = (const float*)d_in[10];
    const float* bih2 = (const float*)d_in[11];
    const float* bhh2 = (const float*)d_in[12];
    const float* Wih3 = (const float*)d_in[13];
    const float* Whh3 = (const float*)d_in[14];
    const float* bih3 = (const float*)d_in[15];
    const float* bhh3 = (const float*)d_in[16];
    const float* W1   = (const float*)d_in[17];
    const float* b1   = (const float*)d_in[18];
    const float* W2   = (const float*)d_in[19];
    const float* b2   = (const float*)d_in[20];
    float* out = (float*)d_out;

    {
        int total = BB * TT * IN0;
        transpose_x_kernel<<<(total + 255) / 256, 256>>>(x);
    }
    lstm_layer_kernel<IN0><<<NCTA, 256>>>(0, 1, Wih0, Whh0, bih0, bhh0);
    lstm_layer_kernel<HH> <<<NCTA, 256>>>(1, 2, Wih1, Whh1, bih1, bhh1);
    lstm_layer_kernel<HH> <<<NCTA, 256>>>(2, 1, Wih2, Whh2, bih2, bhh2);
    lstm_layer_kernel<HH> <<<NCTA, 256>>>(1, 2, Wih3, Whh3, bih3, bhh3);
    fc_head_kernel<<<(BB + 255) / 256, 256>>>(2, W1, b1, W2, b2, out);
}

// round 4
// speedup vs baseline: 1.5890x; 1.5890x over previous
#include <cuda_runtime.h>

// ---------------------------------------------------------------------------
// LSTMModel: 4-layer LSTM (H=50) over B=1024, T=512, IN=7, + FC(25) + FC(1).
// R4: R1's proven dataflow, NB=4 -> 256 CTAs (2 per SM) for latency hiding.
// Weights in registers (one gate row per thread), c-state in registers,
// h/x staged in shared memory. 2 syncthreads per step.
// ---------------------------------------------------------------------------

#define TT  512
#define BB  1024
#define HH  50
#define GG  200           // 4*H gates
#define NB  4             // batch rows per CTA
#define NCTA (BB / NB)    // 256
#define IN0 7
#define FC1 25

__device__ float g_bufA[TT * BB * HH];
__device__ float g_bufB[TT * BB * HH];
__device__ float g_xT[TT * BB * IN0];

__device__ __forceinline__ float sigmf(float x) {
    return __fdividef(1.0f, 1.0f + __expf(-x));
}
__device__ __forceinline__ float tanhfast(float x) {
    float e = __expf(2.0f * x);
    return 1.0f - __fdividef(2.0f, e + 1.0f);
}

// ---------------------------------------------------------------------------
__global__ void transpose_x_kernel(const float* __restrict__ x) {
    int idx = blockIdx.x * blockDim.x + threadIdx.x;
    if (idx < BB * TT * IN0) {
        int k = idx % IN0;
        int t = (idx / IN0) % TT;
        int b = idx / (IN0 * TT);
        g_xT[(t * BB + b) * IN0 + k] = x[idx];
    }
}

// ---------------------------------------------------------------------------
// One LSTM layer over the whole sequence for a 4-row batch tile.
// ---------------------------------------------------------------------------
template <int KIN>
__global__ void __launch_bounds__(256, 2) lstm_layer_kernel(
    int src, int dst,
    const float* __restrict__ Wih,   // [GG][KIN]
    const float* __restrict__ Whh,   // [GG][HH]
    const float* __restrict__ bih,
    const float* __restrict__ bhh)
{
    const float* __restrict__ in_seq =
        (src == 0) ? g_xT : ((src == 1) ? g_bufA : g_bufB);
    float* __restrict__ out_seq = (dst == 1) ? g_bufA : g_bufB;

    __shared__ __align__(16) float sh_h[HH][NB];
    __shared__ __align__(16) float sh_x[2][KIN][NB];
    __shared__ __align__(16) float sh_g[GG][NB];

    const int tid = threadIdx.x;
    const int b0  = blockIdx.x * NB;

    // ---- per-thread weight row in registers (threads 0..199 own gate rows)
    float wih[KIN], whh[HH];
    float bg = 0.0f;
    if (tid < GG) {
#pragma unroll
        for (int k = 0; k < KIN; k++) wih[k] = Wih[tid * KIN + k];
#pragma unroll
        for (int k = 0; k < HH; k++) whh[k] = Whh[tid * HH + k];
        bg = bih[tid] + bhh[tid];
    }

    // ---- c-state in a register: update thread tid<200 owns (jj = tid>>2, b = tid&3)
    float creg = 0.0f;
    const int jj = tid >> 2;
    const int bu = tid & 3;

    // ---- h0 = 0; stage x(t=0) into buffer 0
    for (int i = tid; i < HH * NB; i += 256)
        (&sh_h[0][0])[i] = 0.0f;
    for (int i = tid; i < KIN * NB; i += 256) {
        int b = i % NB, k = i / NB;
        sh_x[0][k][b] = in_seq[(0 * BB + b0 + b) * KIN + k];
    }
    __syncthreads();

    int buf = 0;
    for (int t = 0; t < TT; t++) {
        // ---- prefetch next timestep's input into a register (KIN*NB <= 200 < 256)
        float pf = 0.0f;
        const bool has_next = (t + 1 < TT);
        if (has_next && tid < KIN * NB) {
            int b = tid % NB, k = tid / NB;
            pf = in_seq[((t + 1) * BB + b0 + b) * KIN + k];
        }

        // ---- gate phase: gates[g][b] = bias + Wih.x + Whh.h  (4 acc chains)
        if (tid < GG) {
            float a0 = bg, a1 = bg, a2 = bg, a3 = bg;
#pragma unroll
            for (int k = 0; k < KIN; k++) {
                float w = wih[k];
                float4 xv = *(const float4*)&sh_x[buf][k][0];
                a0 += w * xv.x; a1 += w * xv.y;
                a2 += w * xv.z; a3 += w * xv.w;
            }
#pragma unroll
            for (int k = 0; k < HH; k++) {
                float w = whh[k];
                float4 hv = *(const float4*)&sh_h[k][0];
                a0 += w * hv.x; a1 += w * hv.y;
                a2 += w * hv.z; a3 += w * hv.w;
            }
            *(float4*)&sh_g[tid][0] = make_float4(a0, a1, a2, a3);
        }

        // ---- park prefetched input into the other x buffer
        if (has_next && tid < KIN * NB) {
            int b = tid % NB, k = tid / NB;
            sh_x[buf ^ 1][k][b] = pf;
        }
        __syncthreads();

        // ---- update phase: 200 threads, thread = (unit jj, batch row bu)
        if (tid < GG) {
            float ig = sigmf(sh_g[jj][bu]);
            float fg = sigmf(sh_g[HH + jj][bu]);
            float gg = tanhfast(sh_g[2 * HH + jj][bu]);
            float og = sigmf(sh_g[3 * HH + jj][bu]);
            creg = fg * creg + ig * gg;
            float h = og * tanhfast(creg);
            sh_h[jj][bu] = h;
            out_seq[(t * BB + b0 + bu) * HH + jj] = h;
        }
        buf ^= 1;
        __syncthreads();
    }
}

// ---------------------------------------------------------------------------
__global__ void fc_head_kernel(int src,
                               const float* __restrict__ W1,
                               const float* __restrict__ b1,
                               const float* __restrict__ W2,
                               const float* __restrict__ b2,
                               float* __restrict__ out)
{
    const float* __restrict__ hseq = (src == 1) ? g_bufA : g_bufB;
    __shared__ float sW1[FC1 * HH];
    __shared__ float sW2[FC1];
    __shared__ float sb1[FC1];

    int tid = threadIdx.x;
    for (int i = tid; i < FC1 * HH; i += 256) sW1[i] = W1[i];
    if (tid < FC1) { sW2[tid] = W2[tid]; sb1[tid] = b1[tid]; }
    __syncthreads();

    int b = blockIdx.x * blockDim.x + tid;
    if (b < BB) {
        const float* h = &hseq[((TT - 1) * BB + b) * HH];
        float hreg[HH];
#pragma unroll
        for (int k = 0; k < HH; k++) hreg[k] = h[k];
        float o = b2[0];
#pragma unroll
        for (int j = 0; j < FC1; j++) {
            float a = sb1[j];
#pragma unroll
            for (int k = 0; k < HH; k++) a += sW1[j * HH + k] * hreg[k];
            o += sW2[j] * fmaxf(a, 0.0f);
        }
        out[b] = o;
    }
}

// ---------------------------------------------------------------------------
extern "C" void kernel_launch(void* const* d_in, const int* in_sizes, int n_in,
                              void* d_out, int out_size)
{
    const float* x    = (const float*)d_in[0];
    const float* Wih0 = (const float*)d_in[1];
    const float* Whh0 = (const float*)d_in[2];
    const float* bih0 = (const float*)d_in[3];
    const float* bhh0 = (const float*)d_in[4];
    const float* Wih1 = (const float*)d_in[5];
    const float* Whh1 = (const float*)d_in[6];
    const float* bih1 = (const float*)d_in[7];
    const float* bhh1 = (const float*)d_in[8];
    const float* Wih2 = (const float*)d_in[9];
    const float* Whh2 = (const float*)d_in[10];
    const float* bih2 = (const float*)d_in[11];
    const float* bhh2 = (const float*)d_in[12];
    const float* Wih3 = (const float*)d_in[13];
    const float* Whh3 = (const float*)d_in[14];
    const float* bih3 = (const float*)d_in[15];
    const float* bhh3 = (const float*)d_in[16];
    const float* W1   = (const float*)d_in[17];
    const float* b1   = (const float*)d_in[18];
    const float* W2   = (const float*)d_in[19];
    const float* b2   = (const float*)d_in[20];
    float* out = (float*)d_out;

    {
        int total = BB * TT * IN0;
        transpose_x_kernel<<<(total + 255) / 256, 256>>>(x);
    }
    lstm_layer_kernel<IN0><<<NCTA, 256>>>(0, 1, Wih0, Whh0, bih0, bhh0);
    lstm_layer_kernel<HH> <<<NCTA, 256>>>(1, 2, Wih1, Whh1, bih1, bhh1);
    lstm_layer_kernel<HH> <<<NCTA, 256>>>(2, 1, Wih2, Whh2, bih2, bhh2);
    lstm_layer_kernel<HH> <<<NCTA, 256>>>(1, 2, Wih3, Whh3, bih3, bhh3);
    fc_head_kernel<<<(BB + 255) / 256, 256>>>(2, W1, b1, W2, b2, out);
}